// round 16
// baseline (speedup 1.0000x reference)
#include <cuda_runtime.h>
#include <cuda_fp16.h>
#include <math.h>

// Problem constants (shapes fixed by the dataset)
#define MAXM 50000
#define MAXE 600000
#define MAXN 100000
// D = 128. fp16 feature row = 256 B = 16 x uint4

// ---------------- device scratch (static: no allocations allowed) -----------
__device__ float  g_deg[MAXM];
__device__ float  g_dis[MAXM];
__device__ int    g_cnt[MAXM];
__device__ int    g_rowptr[MAXM + 1];
__device__ int    g_cursor[MAXM];
__device__ int    g_bsum[64];
__device__ int    g_sync1;
__device__ int    g_sync2;
__device__ float2 g_cw[MAXE];        // packed (col as bits, normalized weight)
__device__ uint4  g_h0[MAXM * 16];   // fp16 features ping (12.8 MB)
__device__ uint4  g_h1[MAXM * 16];   // fp16 features pong (12.8 MB)
__device__ int    g_srcmap[MAXN];    // zero-init: 0 = not propagated, else m+1

// fp16 transposed weights (converted per-launch in k_init)
__device__ __half g_w1t[64 * 136];   // W1t[j][k], j<64, k<128, stride 136
__device__ __half g_w2t[32 * 72];    // W2t[j][k], j<32, k<64,  stride 72
__device__ __half g_w3t[24 * 40];    // W3t[j][k], j<24 (21 real), k<32, stride 40

// ---------------- preprocessing kernels ------------------------------------
__global__ void k_init(int M,
                       const float* __restrict__ W1,
                       const float* __restrict__ W2,
                       const float* __restrict__ W3) {
    int i = blockIdx.x * blockDim.x + threadIdx.x;
    if (i == 0) { g_sync1 = 0; g_sync2 = 0; }
    if (i < M) { g_deg[i] = 0.f; g_cnt[i] = 0; }
    // fp16 transposed weight conversion (11008 threads' worth)
    if (i < 8192) {                       // W1: j = i>>7, k = i&127
        int j = i >> 7, k = i & 127;
        g_w1t[j * 136 + k] = __float2half(W1[k * 64 + j]);
    } else if (i < 8192 + 2048) {         // W2
        int i2 = i - 8192;
        int j = i2 >> 6, k = i2 & 63;
        g_w2t[j * 72 + k] = __float2half(W2[k * 32 + j]);
    } else if (i < 8192 + 2048 + 768) {   // W3 (pad j 21..23 with zeros)
        int i3 = i - 8192 - 2048;
        int j = i3 >> 5, k = i3 & 31;
        g_w3t[j * 40 + k] = (j < 21) ? __float2half(W3[k * 21 + j]) : __half(0.f);
    }
}

// degree/count accumulation + (fused) subset gather fp32->fp16 + srcmap
__global__ void k_degcnt_gather(const int* __restrict__ row,
                                const float* __restrict__ val, int E,
                                const float* __restrict__ features,
                                const int* __restrict__ index, int M) {
    int e = blockIdx.x * blockDim.x + threadIdx.x;
    if (e < E) {
        int r = row[e];
        atomicAdd(&g_deg[r], val[e]);
        atomicAdd(&g_cnt[r], 1);
    }
    // gather: M*32 float4 items, grid-stride (independent of CSR chain)
    int nth = gridDim.x * blockDim.x;
    for (int i = e; i < M * 32; i += nth) {
        int m = i >> 5;
        int q = i & 31;
        int src = index[m];
        if (q == 0) g_srcmap[src] = m + 1;
        float4 v = ((const float4*)features)[(size_t)src * 32 + q];
        uint2 o;
        *(__half2*)&o.x = __floats2half2_rn(v.x, v.y);
        *(__half2*)&o.y = __floats2half2_rn(v.z, v.w);
        ((uint2*)g_h0)[m * 32 + q] = o;
    }
}

// ---- fused scan + CSR scatter (single kernel, two spin grid-barriers) ------
// 49 blocks x 1024 threads: all co-resident in wave 1 -> spin is deadlock-free.
__device__ __forceinline__ void gridbar(int* ctr, int nb, int t) {
    __syncthreads();
    if (t == 0) {
        __threadfence();
        atomicAdd(ctr, 1);
        while (atomicAdd(ctr, 0) < nb) { }
    }
    __syncthreads();
}

__global__ void __launch_bounds__(1024) k_scan_scatter(
    const int* __restrict__ erow, const int* __restrict__ ecol,
    const float* __restrict__ eval_, int M, int E, int nb) {
    __shared__ int sh[1024];
    __shared__ int bofs[64];
    int t = threadIdx.x;
    int b = blockIdx.x;
    int i = b * 1024 + t;

    if (i < M) g_dis[i] = rsqrtf(g_deg[i] + 1e-8f);
    int v = (i < M) ? g_cnt[i] : 0;
    sh[t] = v;
    __syncthreads();
    for (int off = 1; off < 1024; off <<= 1) {
        int x = (t >= off) ? sh[t - off] : 0;
        __syncthreads();
        sh[t] += x;
        __syncthreads();
    }
    int incl = sh[t];
    if (t == 1023) g_bsum[b] = incl;

    gridbar(&g_sync1, nb, t);              // all block totals published

    if (t == 0) {
        int s = 0;
        for (int j = 0; j < nb; j++) {
            int bv = *((volatile int*)&g_bsum[j]);
            bofs[j] = s;
            s += bv;
        }
    }
    __syncthreads();
    if (i < M) {
        int r0 = incl - v + bofs[b];
        g_rowptr[i] = r0;
        g_cursor[i] = r0;
    }
    if (i == 0) g_rowptr[M] = E;

    gridbar(&g_sync2, nb, t);              // all cursors finalized

    // scatter: grid-stride with 4 independent atomic chains per thread.
    // g_dis read via __ldcg (L2) — written by other SMs earlier this kernel.
    int nth = nb * 1024;
    int tid = b * 1024 + t;
    for (int e0 = tid; e0 < E; e0 += 4 * nth) {
        int ea = e0, eb = e0 + nth, ec = e0 + 2 * nth, ed = e0 + 3 * nth;
        int ra = 0, ca = 0, rb = 0, cb = 0, rc = 0, cc = 0, rd = 0, cd = 0;
        float va = 0.f, vb = 0.f, vc = 0.f, vd = 0.f;
        bool ba = ea < E, bb = eb < E, bc = ec < E, bd = ed < E;
        if (ba) { ra = erow[ea]; ca = ecol[ea]; va = eval_[ea]; }
        if (bb) { rb = erow[eb]; cb = ecol[eb]; vb = eval_[eb]; }
        if (bc) { rc = erow[ec]; cc = ecol[ec]; vc = eval_[ec]; }
        if (bd) { rd = erow[ed]; cd = ecol[ed]; vd = eval_[ed]; }
        if (ba) {
            float nv = va * __ldcg(g_dis + ra) * __ldcg(g_dis + ca);
            int p = atomicAdd(&g_cursor[ra], 1);
            g_cw[p] = make_float2(__int_as_float(ca), nv);
        }
        if (bb) {
            float nv = vb * __ldcg(g_dis + rb) * __ldcg(g_dis + cb);
            int p = atomicAdd(&g_cursor[rb], 1);
            g_cw[p] = make_float2(__int_as_float(cb), nv);
        }
        if (bc) {
            float nv = vc * __ldcg(g_dis + rc) * __ldcg(g_dis + cc);
            int p = atomicAdd(&g_cursor[rc], 1);
            g_cw[p] = make_float2(__int_as_float(cc), nv);
        }
        if (bd) {
            float nv = vd * __ldcg(g_dis + rd) * __ldcg(g_dis + cd);
            int p = atomicAdd(&g_cursor[rd], 1);
            g_cw[p] = make_float2(__int_as_float(cd), nv);
        }
    }
}

// ---------------- SpMM: 2 rows per warp (16 lanes x 16B), fp32 accum --------
__device__ __forceinline__ void acc8(float* acc, uint4 v, float wgt) {
    float2 f;
    f = __half22float2(*(__half2*)&v.x);
    acc[0] = fmaf(wgt, f.x, acc[0]); acc[1] = fmaf(wgt, f.y, acc[1]);
    f = __half22float2(*(__half2*)&v.y);
    acc[2] = fmaf(wgt, f.x, acc[2]); acc[3] = fmaf(wgt, f.y, acc[3]);
    f = __half22float2(*(__half2*)&v.z);
    acc[4] = fmaf(wgt, f.x, acc[4]); acc[5] = fmaf(wgt, f.y, acc[5]);
    f = __half22float2(*(__half2*)&v.w);
    acc[6] = fmaf(wgt, f.x, acc[6]); acc[7] = fmaf(wgt, f.y, acc[7]);
}

__global__ void __launch_bounds__(256) k_spmm(int srcsel, int M) {
    const uint4* __restrict__ src = srcsel ? (const uint4*)g_h1 : (const uint4*)g_h0;
    uint4* __restrict__ dst       = srcsel ? (uint4*)g_h0       : (uint4*)g_h1;
    int gw   = (blockIdx.x * blockDim.x + threadIdx.x) >> 5;
    int half = (threadIdx.x >> 4) & 1;
    int l    = threadIdx.x & 15;
    int r    = gw * 2 + half;
    int e = 0, end = 0;
    if (r < M) { e = g_rowptr[r]; end = g_rowptr[r + 1]; }
    float acc[8] = {0.f, 0.f, 0.f, 0.f, 0.f, 0.f, 0.f, 0.f};

    for (; e + 4 <= end; e += 4) {
        float2 p0 = __ldg(g_cw + e);
        float2 p1 = __ldg(g_cw + e + 1);
        float2 p2 = __ldg(g_cw + e + 2);
        float2 p3 = __ldg(g_cw + e + 3);
        uint4 v0 = __ldg(src + __float_as_int(p0.x) * 16 + l);
        uint4 v1 = __ldg(src + __float_as_int(p1.x) * 16 + l);
        uint4 v2 = __ldg(src + __float_as_int(p2.x) * 16 + l);
        uint4 v3 = __ldg(src + __float_as_int(p3.x) * 16 + l);
        acc8(acc, v0, p0.y); acc8(acc, v1, p1.y);
        acc8(acc, v2, p2.y); acc8(acc, v3, p3.y);
    }
    for (; e < end; e++) {
        float2 p0 = __ldg(g_cw + e);
        uint4 v0 = __ldg(src + __float_as_int(p0.x) * 16 + l);
        acc8(acc, v0, p0.y);
    }
    if (r < M) {
        uint4 o;
        *(__half2*)&o.x = __floats2half2_rn(acc[0], acc[1]);
        *(__half2*)&o.y = __floats2half2_rn(acc[2], acc[3]);
        *(__half2*)&o.z = __floats2half2_rn(acc[4], acc[5]);
        *(__half2*)&o.w = __floats2half2_rn(acc[6], acc[7]);
        dst[r * 16 + l] = o;
    }
}

// ---------------- fused MLP head — tensor core (mma.sync m16n8k16) ----------
__device__ __forceinline__ float leaky(float v) { return v > 0.f ? v : 0.01f * v; }

__device__ __forceinline__ void mma16816(float* d, unsigned a0, unsigned a1,
                                         unsigned a2, unsigned a3,
                                         unsigned b0, unsigned b1) {
    asm volatile(
        "mma.sync.aligned.m16n8k16.row.col.f32.f16.f16.f32 "
        "{%0,%1,%2,%3}, {%4,%5,%6,%7}, {%8,%9}, {%0,%1,%2,%3};"
        : "+f"(d[0]), "+f"(d[1]), "+f"(d[2]), "+f"(d[3])
        : "r"(a0), "r"(a1), "r"(a2), "r"(a3), "r"(b0), "r"(b1));
}
__device__ __forceinline__ unsigned lds32(const __half* p) {
    return *(const unsigned*)p;
}

// 64 nodes/block, 256 threads = 8 warps.
__global__ void __launch_bounds__(256) k_mlp(
    const float* __restrict__ feat,
    const float* __restrict__ b1, const float* __restrict__ b2,
    const float* __restrict__ b3, const float* __restrict__ W4,
    float* __restrict__ out, int Ntot)
{
    __shared__ __align__(16) char smarena[17408 + 9216];
    __half* xh  = (__half*)smarena;              // [64][136]
    __half* h1h = (__half*)(smarena + 17408);    // [64][72]
    __half* h2h = (__half*)smarena;              // [64][40]   (after GEMM2)
    __half* h3h = (__half*)(smarena + 17408);    // [64][36]   (after GEMM3)

    int t  = threadIdx.x;
    int nb = blockIdx.x * 64;

    // ---- stage x as fp16: xh[n][k] ----
    for (int i = t; i < 64 * 32; i += 256) {
        int n  = i >> 5;
        int c4 = i & 31;
        int gn = nb + n;
        uint2 o = make_uint2(0u, 0u);
        if (gn < Ntot) {
            int sm_ = g_srcmap[gn];
            if (sm_ > 0) {
                o = __ldg(((const uint2*)g_h1) + (size_t)(sm_ - 1) * 32 + c4);
            } else {
                float4 v = __ldg(((const float4*)feat) + (size_t)gn * 32 + c4);
                *(__half2*)&o.x = __floats2half2_rn(v.x, v.y);
                *(__half2*)&o.y = __floats2half2_rn(v.z, v.w);
            }
        }
        *(uint2*)&xh[n * 136 + c4 * 4] = o;
    }
    __syncthreads();

    int lane = t & 31, w = t >> 5;
    int r  = lane >> 2;          // fragment row / B col within n8
    int q2 = (lane & 3) * 2;     // fragment k-pair offset

    // ---- GEMM1 (mma): [64x128] @ W1t -> h1 [64x64] ----
    {
        int m0 = (w & 3) * 16, n0 = (w >> 2) * 32;
        float d[4][4];
#pragma unroll
        for (int i = 0; i < 4; i++) { d[i][0] = d[i][1] = d[i][2] = d[i][3] = 0.f; }
#pragma unroll
        for (int ks = 0; ks < 8; ks++) {
            int kb = ks * 16;
            const __half* ar = &xh[(m0 + r) * 136 + kb + q2];
            unsigned A0 = lds32(ar);
            unsigned A1 = lds32(ar + 8 * 136);
            unsigned A2 = lds32(ar + 8);
            unsigned A3 = lds32(ar + 8 * 136 + 8);
#pragma unroll
            for (int nt = 0; nt < 4; nt++) {
                const __half* br = &g_w1t[(n0 + nt * 8 + r) * 136 + kb + q2];
                unsigned B0 = lds32(br);
                unsigned B1 = lds32(br + 8);
                mma16816(d[nt], A0, A1, A2, A3, B0, B1);
            }
        }
#pragma unroll
        for (int nt = 0; nt < 4; nt++) {
            int c0 = n0 + nt * 8 + q2;
            float bb0 = __ldg(b1 + c0), bb1 = __ldg(b1 + c0 + 1);
            *(__half2*)&h1h[(m0 + r) * 72 + c0] =
                __floats2half2_rn(leaky(d[nt][0] + bb0), leaky(d[nt][1] + bb1));
            *(__half2*)&h1h[(m0 + r + 8) * 72 + c0] =
                __floats2half2_rn(leaky(d[nt][2] + bb0), leaky(d[nt][3] + bb1));
        }
    }
    __syncthreads();

    // ---- GEMM2 (mma): [64x64] @ W2t -> h2 [64x32] (h2h aliases xh) ----
    {
        int m0 = (w & 3) * 16, n0 = (w >> 2) * 16;
        float d[2][4];
#pragma unroll
        for (int i = 0; i < 2; i++) { d[i][0] = d[i][1] = d[i][2] = d[i][3] = 0.f; }
#pragma unroll
        for (int ks = 0; ks < 4; ks++) {
            int kb = ks * 16;
            const __half* ar = &h1h[(m0 + r) * 72 + kb + q2];
            unsigned A0 = lds32(ar);
            unsigned A1 = lds32(ar + 8 * 72);
            unsigned A2 = lds32(ar + 8);
            unsigned A3 = lds32(ar + 8 * 72 + 8);
#pragma unroll
            for (int nt = 0; nt < 2; nt++) {
                const __half* br = &g_w2t[(n0 + nt * 8 + r) * 72 + kb + q2];
                unsigned B0 = lds32(br);
                unsigned B1 = lds32(br + 8);
                mma16816(d[nt], A0, A1, A2, A3, B0, B1);
            }
        }
        __syncthreads();   // xh reads done; h2h may alias it
#pragma unroll
        for (int nt = 0; nt < 2; nt++) {
            int c0 = n0 + nt * 8 + q2;
            float bb0 = __ldg(b2 + c0), bb1 = __ldg(b2 + c0 + 1);
            *(__half2*)&h2h[(m0 + r) * 40 + c0] =
                __floats2half2_rn(leaky(d[nt][0] + bb0), leaky(d[nt][1] + bb1));
            *(__half2*)&h2h[(m0 + r + 8) * 40 + c0] =
                __floats2half2_rn(leaky(d[nt][2] + bb0), leaky(d[nt][3] + bb1));
        }
    }
    __syncthreads();

    // ---- GEMM3 (mma): [64x32] @ W3t -> h3 [64x24] (h3h aliases h1h) ----
    {
#pragma unroll
        for (int pass = 0; pass < 2; pass++) {
            int tid = w + pass * 8;
            if (tid >= 12) break;
            int m0 = (tid & 3) * 16, ntile = tid >> 2;
            int n0 = ntile * 8;
            float d[4] = {0.f, 0.f, 0.f, 0.f};
#pragma unroll
            for (int ks = 0; ks < 2; ks++) {
                int kb = ks * 16;
                const __half* ar = &h2h[(m0 + r) * 40 + kb + q2];
                unsigned A0 = lds32(ar);
                unsigned A1 = lds32(ar + 8 * 40);
                unsigned A2 = lds32(ar + 8);
                unsigned A3 = lds32(ar + 8 * 40 + 8);
                const __half* br = &g_w3t[(n0 + r) * 40 + kb + q2];
                unsigned B0 = lds32(br);
                unsigned B1 = lds32(br + 8);
                mma16816(d, A0, A1, A2, A3, B0, B1);
            }
            int c0 = n0 + q2;
            float bb0 = (c0 < 21) ? __ldg(b3 + c0) : 0.f;
            float bb1 = (c0 + 1 < 21) ? __ldg(b3 + c0 + 1) : 0.f;
            *(__half2*)&h3h[(m0 + r) * 36 + c0] =
                __floats2half2_rn(leaky(d[0] + bb0), leaky(d[1] + bb1));
            *(__half2*)&h3h[(m0 + r + 8) * 36 + c0] =
                __floats2half2_rn(leaky(d[2] + bb0), leaky(d[3] + bb1));
        }
    }
    __syncthreads();

    // ---- GEMM4 + sigmoid: [64x21] @ W4[21x1] ----
    if (t < 64) {
        int gn = nb + t;
        if (gn < Ntot) {
            float s = 0.f;
#pragma unroll
            for (int k = 0; k < 21; k++)
                s = fmaf(__half2float(h3h[t * 36 + k]), __ldg(W4 + k), s);
            out[gn] = 1.f / (1.f + expf(-s));
        }
    }
}

// ---------------- launch -----------------------------------------------------
extern "C" void kernel_launch(void* const* d_in, const int* in_sizes, int n_in,
                              void* d_out, int out_size) {
    const float* features = (const float*)d_in[0];
    const int*   index    = (const int*)d_in[1];
    const int*   erow     = (const int*)d_in[2];
    const int*   ecol     = (const int*)d_in[3];
    const float* eval_    = (const float*)d_in[4];
    const float* W1 = (const float*)d_in[5];
    const float* b1 = (const float*)d_in[6];
    const float* W2 = (const float*)d_in[7];
    const float* b2 = (const float*)d_in[8];
    const float* W3 = (const float*)d_in[9];
    const float* b3 = (const float*)d_in[10];
    const float* W4 = (const float*)d_in[11];

    int M = in_sizes[1];
    int E = in_sizes[2];
    int N = out_size;            // [N, 1] fp32 output
    float* out = (float*)d_out;

    const int TB = 256;
    int scanBlocks = (M + 1023) / 1024;   // 49 for M=50000 (g_bsum holds 64)

    // 1
    k_init<<<(M + TB - 1) / TB, TB>>>(M, W1, W2, W3);
    // 2 (degree/count atomics + fused feature gather + srcmap)
    k_degcnt_gather<<<(E + TB - 1) / TB, TB>>>(erow, eval_, E, features, index, M);
    // 3 (fused scan + CSR scatter, spin grid-barriers)
    k_scan_scatter<<<scanBlocks, 1024>>>(erow, ecol, eval_, M, E, scanBlocks);

    // 4-6: SpMM layers (launch #4 is now the ncu-profiled node)
    int spmmBlocks = (M + 15) / 16;       // 2 rows per warp, 8 warps per block
    k_spmm<<<spmmBlocks, TB>>>(0, M);     // h0 -> h1
    k_spmm<<<spmmBlocks, TB>>>(1, M);     // h1 -> h0
    k_spmm<<<spmmBlocks, TB>>>(0, M);     // h0 -> h1  (final in h1)

    // 7
    k_mlp<<<(N + 63) / 64, 256>>>(features, b1, b2, b3, W4, out, N);
}

// round 17
// speedup vs baseline: 1.1138x; 1.1138x over previous
#include <cuda_runtime.h>
#include <cuda_fp16.h>
#include <math.h>

// Problem constants (shapes fixed by the dataset)
#define MAXM 50000
#define MAXE 600000
#define MAXN 100000
// D = 128. fp16 feature row = 256 B = 16 x uint4

// ---------------- device scratch (static: no allocations allowed) -----------
__device__ float  g_deg[MAXM];
__device__ float  g_dis[MAXM];
__device__ int    g_cnt[MAXM];
__device__ int    g_rowptr[MAXM + 1];
__device__ int    g_cursor[MAXM];
__device__ int    g_bsum[64];
__device__ float2 g_cw[MAXE];        // packed (col as bits, normalized weight)
__device__ uint4  g_h0[MAXM * 16];   // fp16 features ping (12.8 MB)
__device__ uint4  g_h1[MAXM * 16];   // fp16 features pong (12.8 MB)
__device__ int    g_srcmap[MAXN];    // zero-init: 0 = not propagated, else m+1

// fp16 transposed weights (converted per-launch in k_init)
__device__ __half g_w1t[64 * 136];   // W1t[j][k], j<64, k<128, stride 136
__device__ __half g_w2t[32 * 72];    // W2t[j][k], j<32, k<64,  stride 72
__device__ __half g_w3t[24 * 40];    // W3t[j][k], j<24 (21 real), k<32, stride 40

// ---------------- preprocessing kernels ------------------------------------
__global__ void k_init(int M,
                       const float* __restrict__ W1,
                       const float* __restrict__ W2,
                       const float* __restrict__ W3) {
    int i = blockIdx.x * blockDim.x + threadIdx.x;
    if (i < M) { g_deg[i] = 0.f; g_cnt[i] = 0; }
    // fp16 transposed weight conversion (11008 threads' worth)
    if (i < 8192) {                       // W1: j = i>>7, k = i&127
        int j = i >> 7, k = i & 127;
        g_w1t[j * 136 + k] = __float2half(W1[k * 64 + j]);
    } else if (i < 8192 + 2048) {         // W2
        int i2 = i - 8192;
        int j = i2 >> 6, k = i2 & 63;
        g_w2t[j * 72 + k] = __float2half(W2[k * 32 + j]);
    } else if (i < 8192 + 2048 + 768) {   // W3 (pad j 21..23 with zeros)
        int i3 = i - 8192 - 2048;
        int j = i3 >> 5, k = i3 & 31;
        g_w3t[j * 40 + k] = (j < 21) ? __float2half(W3[k * 21 + j]) : __half(0.f);
    }
}

// degree/count accumulation + fused subset gather fp32->fp16 + srcmap
__global__ void k_degcnt_gather(const int* __restrict__ row,
                                const float* __restrict__ val, int E,
                                const float* __restrict__ features,
                                const int* __restrict__ index, int M) {
    int e = blockIdx.x * blockDim.x + threadIdx.x;
    if (e < E) {
        int r = row[e];
        atomicAdd(&g_deg[r], val[e]);
        atomicAdd(&g_cnt[r], 1);
    }
    // gather: M*32 float4 items, grid-stride (independent of degree chain)
    int nth = gridDim.x * blockDim.x;
    for (int i = e; i < M * 32; i += nth) {
        int m = i >> 5;
        int q = i & 31;
        int src = index[m];
        if (q == 0) g_srcmap[src] = m + 1;
        float4 v = ((const float4*)features)[(size_t)src * 32 + q];
        uint2 o;
        *(__half2*)&o.x = __floats2half2_rn(v.x, v.y);
        *(__half2*)&o.y = __floats2half2_rn(v.z, v.w);
        ((uint2*)g_h0)[m * 32 + q] = o;
    }
}

// Phase 1 scan (+ fused d^-1/2): per-block local exclusive scan of g_cnt.
__global__ void __launch_bounds__(1024) k_scan1(int M) {
    __shared__ int sh[1024];
    int t = threadIdx.x;
    int i = blockIdx.x * 1024 + t;
    if (i < M) g_dis[i] = rsqrtf(g_deg[i] + 1e-8f);
    int v = (i < M) ? g_cnt[i] : 0;
    sh[t] = v;
    __syncthreads();
    for (int off = 1; off < 1024; off <<= 1) {
        int x = (t >= off) ? sh[t - off] : 0;
        __syncthreads();
        sh[t] += x;
        __syncthreads();
    }
    int incl = sh[t];
    if (i < M) g_rowptr[i] = incl - v;          // local exclusive
    if (t == 1023) g_bsum[blockIdx.x] = incl;   // block total
}

// Phase 2+3 fused: each block redundantly scans the block totals in smem,
// then finalizes rowptr/cursor for its slice.
__global__ void k_scan3(int M, int E, int nb) {
    __shared__ int sh[64];
    int t = threadIdx.x;
    if (t < 64) sh[t] = (t < nb) ? g_bsum[t] : 0;
    __syncthreads();
    if (t == 0) {
        int s = 0;
        for (int j = 0; j < nb; j++) { int v = sh[j]; sh[j] = s; s += v; }
    }
    __syncthreads();
    int i = blockIdx.x * blockDim.x + t;
    if (i < M) {
        int v = g_rowptr[i] + sh[i >> 10];
        g_rowptr[i] = v;
        g_cursor[i] = v;
    }
    if (i == 0) g_rowptr[M] = E;
}

// scatter edges into CSR slots, fusing the symmetric-normalization multiply
__global__ void k_scatter(const int* __restrict__ row, const int* __restrict__ col,
                          const float* __restrict__ val, int E) {
    int e = blockIdx.x * blockDim.x + threadIdx.x;
    if (e < E) {
        int r = row[e];
        int c = col[e];
        float nv = val[e] * g_dis[r] * g_dis[c];
        int p = atomicAdd(&g_cursor[r], 1);
        g_cw[p] = make_float2(__int_as_float(c), nv);
    }
}

// ---------------- SpMM: 2 rows/warp, 8-deep gather pipeline, fp32 accum -----
__device__ __forceinline__ void acc8(float* acc, uint4 v, float wgt) {
    float2 f;
    f = __half22float2(*(__half2*)&v.x);
    acc[0] = fmaf(wgt, f.x, acc[0]); acc[1] = fmaf(wgt, f.y, acc[1]);
    f = __half22float2(*(__half2*)&v.y);
    acc[2] = fmaf(wgt, f.x, acc[2]); acc[3] = fmaf(wgt, f.y, acc[3]);
    f = __half22float2(*(__half2*)&v.z);
    acc[4] = fmaf(wgt, f.x, acc[4]); acc[5] = fmaf(wgt, f.y, acc[5]);
    f = __half22float2(*(__half2*)&v.w);
    acc[6] = fmaf(wgt, f.x, acc[6]); acc[7] = fmaf(wgt, f.y, acc[7]);
}

__global__ void __launch_bounds__(256) k_spmm(int srcsel, int M) {
    const uint4* __restrict__ src = srcsel ? (const uint4*)g_h1 : (const uint4*)g_h0;
    uint4* __restrict__ dst       = srcsel ? (uint4*)g_h0       : (uint4*)g_h1;
    int gw   = (blockIdx.x * blockDim.x + threadIdx.x) >> 5;
    int half = (threadIdx.x >> 4) & 1;
    int l    = threadIdx.x & 15;
    int r    = gw * 2 + half;
    int e = 0, end = 0;
    if (r < M) { e = g_rowptr[r]; end = g_rowptr[r + 1]; }
    float acc[8] = {0.f, 0.f, 0.f, 0.f, 0.f, 0.f, 0.f, 0.f};

    // 8 independent gathers in flight
    for (; e + 8 <= end; e += 8) {
        float2 p[8];
        uint4  v[8];
#pragma unroll
        for (int j = 0; j < 8; j++) p[j] = __ldg(g_cw + e + j);
#pragma unroll
        for (int j = 0; j < 8; j++)
            v[j] = __ldg(src + __float_as_int(p[j].x) * 16 + l);
#pragma unroll
        for (int j = 0; j < 8; j++) acc8(acc, v[j], p[j].y);
    }
    if (e + 4 <= end) {
        float2 p[4];
        uint4  v[4];
#pragma unroll
        for (int j = 0; j < 4; j++) p[j] = __ldg(g_cw + e + j);
#pragma unroll
        for (int j = 0; j < 4; j++)
            v[j] = __ldg(src + __float_as_int(p[j].x) * 16 + l);
#pragma unroll
        for (int j = 0; j < 4; j++) acc8(acc, v[j], p[j].y);
        e += 4;
    }
    for (; e < end; e++) {
        float2 p0 = __ldg(g_cw + e);
        uint4 v0 = __ldg(src + __float_as_int(p0.x) * 16 + l);
        acc8(acc, v0, p0.y);
    }
    if (r < M) {
        uint4 o;
        *(__half2*)&o.x = __floats2half2_rn(acc[0], acc[1]);
        *(__half2*)&o.y = __floats2half2_rn(acc[2], acc[3]);
        *(__half2*)&o.z = __floats2half2_rn(acc[4], acc[5]);
        *(__half2*)&o.w = __floats2half2_rn(acc[6], acc[7]);
        dst[r * 16 + l] = o;
    }
}

// ---------------- fused MLP head — tensor core (mma.sync m16n8k16) ----------
__device__ __forceinline__ float leaky(float v) { return v > 0.f ? v : 0.01f * v; }

__device__ __forceinline__ void mma16816(float* d, unsigned a0, unsigned a1,
                                         unsigned a2, unsigned a3,
                                         unsigned b0, unsigned b1) {
    asm volatile(
        "mma.sync.aligned.m16n8k16.row.col.f32.f16.f16.f32 "
        "{%0,%1,%2,%3}, {%4,%5,%6,%7}, {%8,%9}, {%0,%1,%2,%3};"
        : "+f"(d[0]), "+f"(d[1]), "+f"(d[2]), "+f"(d[3])
        : "r"(a0), "r"(a1), "r"(a2), "r"(a3), "r"(b0), "r"(b1));
}
__device__ __forceinline__ unsigned lds32(const __half* p) {
    return *(const unsigned*)p;
}

// 64 nodes/block, 256 threads = 8 warps.
__global__ void __launch_bounds__(256) k_mlp(
    const float* __restrict__ feat,
    const float* __restrict__ b1, const float* __restrict__ b2,
    const float* __restrict__ b3, const float* __restrict__ W4,
    float* __restrict__ out, int Ntot)
{
    __shared__ __align__(16) char smarena[17408 + 9216];
    __half* xh  = (__half*)smarena;              // [64][136]
    __half* h1h = (__half*)(smarena + 17408);    // [64][72]
    __half* h2h = (__half*)smarena;              // [64][40]   (after GEMM2)
    __half* h3h = (__half*)(smarena + 17408);    // [64][36]   (after GEMM3)

    int t  = threadIdx.x;
    int nb = blockIdx.x * 64;

    // ---- stage x as fp16: xh[n][k] ----
    for (int i = t; i < 64 * 32; i += 256) {
        int n  = i >> 5;
        int c4 = i & 31;
        int gn = nb + n;
        uint2 o = make_uint2(0u, 0u);
        if (gn < Ntot) {
            int sm_ = g_srcmap[gn];
            if (sm_ > 0) {
                o = __ldg(((const uint2*)g_h1) + (size_t)(sm_ - 1) * 32 + c4);
            } else {
                float4 v = __ldg(((const float4*)feat) + (size_t)gn * 32 + c4);
                *(__half2*)&o.x = __floats2half2_rn(v.x, v.y);
                *(__half2*)&o.y = __floats2half2_rn(v.z, v.w);
            }
        }
        *(uint2*)&xh[n * 136 + c4 * 4] = o;
    }
    __syncthreads();

    int lane = t & 31, w = t >> 5;
    int r  = lane >> 2;          // fragment row / B col within n8
    int q2 = (lane & 3) * 2;     // fragment k-pair offset

    // ---- GEMM1 (mma): [64x128] @ W1t -> h1 [64x64] ----
    {
        int m0 = (w & 3) * 16, n0 = (w >> 2) * 32;
        float d[4][4];
#pragma unroll
        for (int i = 0; i < 4; i++) { d[i][0] = d[i][1] = d[i][2] = d[i][3] = 0.f; }
#pragma unroll
        for (int ks = 0; ks < 8; ks++) {
            int kb = ks * 16;
            const __half* ar = &xh[(m0 + r) * 136 + kb + q2];
            unsigned A0 = lds32(ar);
            unsigned A1 = lds32(ar + 8 * 136);
            unsigned A2 = lds32(ar + 8);
            unsigned A3 = lds32(ar + 8 * 136 + 8);
#pragma unroll
            for (int nt = 0; nt < 4; nt++) {
                const __half* br = &g_w1t[(n0 + nt * 8 + r) * 136 + kb + q2];
                unsigned B0 = lds32(br);
                unsigned B1 = lds32(br + 8);
                mma16816(d[nt], A0, A1, A2, A3, B0, B1);
            }
        }
#pragma unroll
        for (int nt = 0; nt < 4; nt++) {
            int c0 = n0 + nt * 8 + q2;
            float bb0 = __ldg(b1 + c0), bb1 = __ldg(b1 + c0 + 1);
            *(__half2*)&h1h[(m0 + r) * 72 + c0] =
                __floats2half2_rn(leaky(d[nt][0] + bb0), leaky(d[nt][1] + bb1));
            *(__half2*)&h1h[(m0 + r + 8) * 72 + c0] =
                __floats2half2_rn(leaky(d[nt][2] + bb0), leaky(d[nt][3] + bb1));
        }
    }
    __syncthreads();

    // ---- GEMM2 (mma): [64x64] @ W2t -> h2 [64x32] (h2h aliases xh) ----
    {
        int m0 = (w & 3) * 16, n0 = (w >> 2) * 16;
        float d[2][4];
#pragma unroll
        for (int i = 0; i < 2; i++) { d[i][0] = d[i][1] = d[i][2] = d[i][3] = 0.f; }
#pragma unroll
        for (int ks = 0; ks < 4; ks++) {
            int kb = ks * 16;
            const __half* ar = &h1h[(m0 + r) * 72 + kb + q2];
            unsigned A0 = lds32(ar);
            unsigned A1 = lds32(ar + 8 * 72);
            unsigned A2 = lds32(ar + 8);
            unsigned A3 = lds32(ar + 8 * 72 + 8);
#pragma unroll
            for (int nt = 0; nt < 2; nt++) {
                const __half* br = &g_w2t[(n0 + nt * 8 + r) * 72 + kb + q2];
                unsigned B0 = lds32(br);
                unsigned B1 = lds32(br + 8);
                mma16816(d[nt], A0, A1, A2, A3, B0, B1);
            }
        }
        __syncthreads();   // xh reads done; h2h may alias it
#pragma unroll
        for (int nt = 0; nt < 2; nt++) {
            int c0 = n0 + nt * 8 + q2;
            float bb0 = __ldg(b2 + c0), bb1 = __ldg(b2 + c0 + 1);
            *(__half2*)&h2h[(m0 + r) * 40 + c0] =
                __floats2half2_rn(leaky(d[nt][0] + bb0), leaky(d[nt][1] + bb1));
            *(__half2*)&h2h[(m0 + r + 8) * 40 + c0] =
                __floats2half2_rn(leaky(d[nt][2] + bb0), leaky(d[nt][3] + bb1));
        }
    }
    __syncthreads();

    // ---- GEMM3 (mma): [64x32] @ W3t -> h3 [64x24] (h3h aliases h1h) ----
    {
#pragma unroll
        for (int pass = 0; pass < 2; pass++) {
            int tid = w + pass * 8;
            if (tid >= 12) break;
            int m0 = (tid & 3) * 16, ntile = tid >> 2;
            int n0 = ntile * 8;
            float d[4] = {0.f, 0.f, 0.f, 0.f};
#pragma unroll
            for (int ks = 0; ks < 2; ks++) {
                int kb = ks * 16;
                const __half* ar = &h2h[(m0 + r) * 40 + kb + q2];
                unsigned A0 = lds32(ar);
                unsigned A1 = lds32(ar + 8 * 40);
                unsigned A2 = lds32(ar + 8);
                unsigned A3 = lds32(ar + 8 * 40 + 8);
                const __half* br = &g_w3t[(n0 + r) * 40 + kb + q2];
                unsigned B0 = lds32(br);
                unsigned B1 = lds32(br + 8);
                mma16816(d, A0, A1, A2, A3, B0, B1);
            }
            int c0 = n0 + q2;
            float bb0 = (c0 < 21) ? __ldg(b3 + c0) : 0.f;
            float bb1 = (c0 + 1 < 21) ? __ldg(b3 + c0 + 1) : 0.f;
            *(__half2*)&h3h[(m0 + r) * 36 + c0] =
                __floats2half2_rn(leaky(d[0] + bb0), leaky(d[1] + bb1));
            *(__half2*)&h3h[(m0 + r + 8) * 36 + c0] =
                __floats2half2_rn(leaky(d[2] + bb0), leaky(d[3] + bb1));
        }
    }
    __syncthreads();

    // ---- GEMM4 + sigmoid: [64x21] @ W4[21x1] ----
    if (t < 64) {
        int gn = nb + t;
        if (gn < Ntot) {
            float s = 0.f;
#pragma unroll
            for (int k = 0; k < 21; k++)
                s = fmaf(__half2float(h3h[t * 36 + k]), __ldg(W4 + k), s);
            out[gn] = 1.f / (1.f + expf(-s));
        }
    }
}

// ---------------- launch -----------------------------------------------------
extern "C" void kernel_launch(void* const* d_in, const int* in_sizes, int n_in,
                              void* d_out, int out_size) {
    const float* features = (const float*)d_in[0];
    const int*   index    = (const int*)d_in[1];
    const int*   erow     = (const int*)d_in[2];
    const int*   ecol     = (const int*)d_in[3];
    const float* eval_    = (const float*)d_in[4];
    const float* W1 = (const float*)d_in[5];
    const float* b1 = (const float*)d_in[6];
    const float* W2 = (const float*)d_in[7];
    const float* b2 = (const float*)d_in[8];
    const float* W3 = (const float*)d_in[9];
    const float* b3 = (const float*)d_in[10];
    const float* W4 = (const float*)d_in[11];

    int M = in_sizes[1];
    int E = in_sizes[2];
    int N = out_size;            // [N, 1] fp32 output
    float* out = (float*)d_out;

    const int TB = 256;
    int scanBlocks = (M + 1023) / 1024;   // 49 for M=50000 (g_bsum holds 64)

    k_init         <<<(M + TB - 1) / TB, TB>>>(M, W1, W2, W3);
    k_degcnt_gather<<<(E + TB - 1) / TB, TB>>>(erow, eval_, E, features, index, M);
    k_scan1        <<<scanBlocks, 1024>>>(M);
    k_scan3        <<<(M + TB - 1) / TB, TB>>>(M, E, scanBlocks);
    k_scatter      <<<(E + TB - 1) / TB, TB>>>(erow, ecol, eval_, E);

    int spmmBlocks = (M + 15) / 16;       // 2 rows per warp, 8 warps per block
    k_spmm<<<spmmBlocks, TB>>>(0, M);     // h0 -> h1
    k_spmm<<<spmmBlocks, TB>>>(1, M);     // h1 -> h0
    k_spmm<<<spmmBlocks, TB>>>(0, M);     // h0 -> h1  (final in h1)

    k_mlp<<<(N + 63) / 64, 256>>>(features, b1, b2, b3, W4, out, N);
}